// round 14
// baseline (speedup 1.0000x reference)
#include <cuda_runtime.h>
#include <cuda_fp16.h>
#include <cstdint>

#define NTOK   131072
#define DIMS   256
#define NCODE  1024
#define TOKB   128
#define TPB    256
#define NCH    32                 // codes per B chunk
#define NCHUNK (NCODE / NCH)      // 32
#define MARGIN 1e-4f

// smem layout (bytes)
#define SA    0                   // A: 128 rows x 256 fp16, stride 512B, swizzled = 64KB
#define SB    65536               // B: 2 x (32 rows x 256 fp16, stride 512B, swizzled) = 32KB
#define SBSZ  16384
#define SESQ  98304               // 1024 f32
#define SR1V  102400              // 2 N-groups x 128 rows each (1KB per array)
#define SR1I  103424
#define SR2V  104448
#define SR2I  105472
#define SR3V  106496
#define SR3I  107520
#define SR4V  108544
#define SR4I  109568
#define SMEM_BYTES 110592

typedef unsigned long long ull;
typedef unsigned int u32;

__device__ float g_esq[NCODE];
__device__ int   g_npair, g_nfull;
__device__ ull   g_pair[NTOK];
__device__ u32   g_full[NTOK];
__device__ u32   g_idx[NTOK];
__device__ __align__(16) __half g_Bh[(size_t)NCODE * DIMS];

__device__ __forceinline__ u32 s2u(const void* p) {
    u32 a; asm("{ .reg .u64 t; cvta.to.shared.u64 t, %1; cvt.u32.u64 %0, t; }" : "=r"(a) : "l"(p)); return a;
}
__device__ __forceinline__ void cpa16(u32 dst, const void* src) {
    asm volatile("cp.async.cg.shared.global [%0], [%1], 16;" :: "r"(dst), "l"(src));
}
#define CPA_COMMIT() asm volatile("cp.async.commit_group;" ::: "memory")
#define CPA_WAIT1()  asm volatile("cp.async.wait_group 1;"  ::: "memory")
#define CPA_WAIT0()  asm volatile("cp.async.wait_group 0;"  ::: "memory")

__device__ __forceinline__ void ldsm4(u32* r, u32 addr) {
    asm volatile("ldmatrix.sync.aligned.m8n8.x4.shared.b16 {%0,%1,%2,%3}, [%4];"
                 : "=r"(r[0]), "=r"(r[1]), "=r"(r[2]), "=r"(r[3]) : "r"(addr));
}
__device__ __forceinline__ void mma16816(float* c, const u32* a, const u32* b) {
    asm volatile("mma.sync.aligned.m16n8k16.row.col.f32.f16.f16.f32 "
                 "{%0,%1,%2,%3}, {%4,%5,%6,%7}, {%8,%9}, {%0,%1,%2,%3};"
                 : "+f"(c[0]), "+f"(c[1]), "+f"(c[2]), "+f"(c[3])
                 : "r"(a[0]), "r"(a[1]), "r"(a[2]), "r"(a[3]), "r"(b[0]), "r"(b[1]));
}
__device__ __forceinline__ u32 packh(float lo, float hi) {    // low 16 <- lo
    u32 r; asm("cvt.rn.f16x2.f32 %0, %1, %2;" : "=r"(r) : "f"(hi), "f"(lo)); return r;
}
__device__ __forceinline__ u32 ordf(float f) {
    u32 u = __float_as_uint(f);
    return (u & 0x80000000u) ? ~u : (u | 0x80000000u);
}
// streaming insert into sorted top-4 (with indices)
__device__ __forceinline__ void ins4(float m, u32 c,
    float &b1, float &b2, float &b3, float &b4,
    u32 &i1, u32 &i2, u32 &i3, u32 &i4)
{
    if (m < b4) {
        if (m < b3) {
            b4 = b3; i4 = i3;
            if (m < b2) {
                b3 = b2; i3 = i2;
                if (m < b1) { b2 = b1; i2 = i1; b1 = m; i1 = c; }
                else        { b2 = m; i2 = c; }
            } else { b3 = m; i3 = c; }
        } else { b4 = m; i4 = c; }
    }
}

// ---------------- merged prep: fp16 codebook + esq ----------------
__global__ __launch_bounds__(256) void prep_kernel(const float* __restrict__ cb) {
    __shared__ float ws[8];
    const int code = blockIdx.x, d = threadIdx.x;
    if (code == 0 && d == 0) { g_npair = 0; g_nfull = 0; }
    float e = cb[(size_t)code * DIMS + d];
    g_Bh[(size_t)code * DIMS + d] = __float2half_rn(e);
    float s = e * e;
#pragma unroll
    for (int o = 16; o > 0; o >>= 1) s += __shfl_xor_sync(~0u, s, o);
    if ((d & 31) == 0) ws[d >> 5] = s;
    __syncthreads();
    if (d == 0) {
        float t = 0.f;
#pragma unroll
        for (int i = 0; i < 8; i++) t += ws[i];
        g_esq[code] = t;
    }
}

// ---------------- main: HMMA GEMM (fp16) + top-4 argmin, TOKB=128, occ 2 ----------------
__global__ __launch_bounds__(TPB, 2) void vq_kernel(const float* __restrict__ z)
{
    extern __shared__ __align__(16) unsigned char smem[];
    const u32 smb = s2u(smem);
    float* esq_s = (float*)(smem + SESQ);
    float* r1v = (float*)(smem + SR1V); u32* r1i = (u32*)(smem + SR1I);
    float* r2v = (float*)(smem + SR2V); u32* r2i = (u32*)(smem + SR2I);
    float* r3v = (float*)(smem + SR3V); u32* r3i = (u32*)(smem + SR3I);
    float* r4v = (float*)(smem + SR4V); u32* r4i = (u32*)(smem + SR4I);

    const int tid = threadIdx.x, lane = tid & 31, wid = tid >> 5;
    const int wm = wid & 3, wn = wid >> 2;      // 4 M-groups (32 rows) x 2 N-groups (16 codes)
    const size_t tokBase = (size_t)blockIdx.x * TOKB;

    // kick B chunk 0 (32 codes x 256 fp16 = 1024 x 16B)
#pragma unroll
    for (int i = 0; i < 4; i++) {
        int flat = tid + i * TPB, row = flat >> 5, g = flat & 31;
        u32 dst = smb + SB + (u32)row * 512 + (u32)((g ^ (row & 7)) << 4);
        cpa16(dst, g_Bh + ((size_t)row * DIMS + g * 8));
    }
    CPA_COMMIT();

    // A: convert z -> fp16 into smem (swizzled), 128 rows x 256
#pragma unroll
    for (int i = 0; i < 16; i++) {
        int flat = tid + i * TPB, row = flat >> 5, g = flat & 31;
        const float4* zp = (const float4*)(z + (tokBase + row) * DIMS + g * 8);
        float4 a = zp[0], b = zp[1];
        u32 h0 = packh(a.x, a.y), h1 = packh(a.z, a.w), h2 = packh(b.x, b.y), h3 = packh(b.z, b.w);
        u32 ah = smb + SA + (u32)row * 512 + (u32)((g ^ (row & 7)) << 4);
        asm volatile("st.shared.v4.b32 [%0], {%1,%2,%3,%4};" :: "r"(ah), "r"(h0), "r"(h1), "r"(h2), "r"(h3));
    }
#pragma unroll
    for (int i = 0; i < 4; i++) esq_s[tid + i * TPB] = g_esq[tid + i * TPB];

    // per-warp ldmatrix bases (fragment maps verified R4-R13)
    const int t8 = lane >> 3;
    u32 aBase[2]; int aSw[2];
#pragma unroll
    for (int mt = 0; mt < 2; mt++) {
        int ar = wm * 32 + mt * 16 + (t8 & 1) * 8 + (lane & 7);
        aSw[mt] = ar & 7; aBase[mt] = smb + SA + (u32)ar * 512;
    }
    const int akt = (lane >> 4) & 1;
    const int br = wn * 16 + (t8 >> 1) * 8 + (lane & 7);
    const int bSw = br & 7, bkt = t8 & 1;
    const u32 bRowOff = (u32)br * 512;

    // top-4 per row-slot (4 slots: mt*2 + acc-row-half)
    float b1v[4], b2v[4], b3v[4], b4v[4];
    u32 b1i[4], b2i[4], b3i[4], b4i[4];
#pragma unroll
    for (int s = 0; s < 4; s++) {
        b1v[s] = b2v[s] = b3v[s] = b4v[s] = 3.4e38f;
        b1i[s] = b2i[s] = b3i[s] = b4i[s] = 0;
    }

    for (int ch = 0; ch < NCHUNK; ch++) {
        if (ch < NCHUNK - 1) {
            const int nc = ch + 1;
#pragma unroll
            for (int i = 0; i < 4; i++) {
                int flat = tid + i * TPB, row = flat >> 5, g = flat & 31;
                u32 dst = smb + SB + (u32)((nc & 1) ? SBSZ : 0) + (u32)row * 512 + (u32)((g ^ (row & 7)) << 4);
                cpa16(dst, g_Bh + ((size_t)(nc * NCH + row) * DIMS + g * 8));
            }
            CPA_COMMIT();
            CPA_WAIT1();
        } else {
            CPA_WAIT0();
        }
        __syncthreads();

        const u32 bb = smb + SB + (u32)((ch & 1) ? SBSZ : 0) + bRowOff;
        float acc[2][2][4];
#pragma unroll
        for (int mt = 0; mt < 2; mt++)
#pragma unroll
            for (int nt = 0; nt < 2; nt++)
#pragma unroll
                for (int i = 0; i < 4; i++) acc[mt][nt][i] = 0.f;

        // software-pipelined fragments
        u32 bF[2][4], aF[2][2][4];
        ldsm4(bF[0], bb + (u32)(((0 + bkt) ^ bSw) << 4));
#pragma unroll
        for (int mt = 0; mt < 2; mt++)
            ldsm4(aF[0][mt], aBase[mt] + (u32)(((0 + akt) ^ aSw[mt]) << 4));

#pragma unroll
        for (int ks = 0; ks < 16; ks++) {
            const int cur = ks & 1, nxt = cur ^ 1;
            if (ks < 15) {
                const int k2 = (ks + 1) * 2;
                ldsm4(bF[nxt], bb + (u32)(((k2 + bkt) ^ bSw) << 4));
#pragma unroll
                for (int mt = 0; mt < 2; mt++)
                    ldsm4(aF[nxt][mt], aBase[mt] + (u32)(((k2 + akt) ^ aSw[mt]) << 4));
            }
#pragma unroll
            for (int mt = 0; mt < 2; mt++) {
                mma16816(acc[mt][0], aF[cur][mt], bF[cur]);
                mma16816(acc[mt][1], aF[cur][mt], bF[cur] + 2);
            }
        }

        // epilogue: m = esq - 2*dot, top-4 insert
#pragma unroll
        for (int mt = 0; mt < 2; mt++)
#pragma unroll
            for (int nt = 0; nt < 2; nt++)
#pragma unroll
                for (int i = 0; i < 4; i++) {
                    int c = ch * NCH + wn * 16 + nt * 8 + 2 * (lane & 3) + (i & 1);
                    float m = fmaf(-2.f, acc[mt][nt][i], esq_s[c]);
                    int s = mt * 2 + (i >> 1);
                    ins4(m, (u32)c, b1v[s], b2v[s], b3v[s], b4v[s],
                         b1i[s], b2i[s], b3i[s], b4i[s]);
                }
        __syncthreads();
    }

    // quad-lane merge (lanes sharing lane>>2 hold the same token row)
#pragma unroll
    for (int s = 0; s < 4; s++) {
#pragma unroll
        for (int x = 1; x <= 2; x <<= 1) {
            float o1 = __shfl_xor_sync(~0u, b1v[s], x); u32 oi1 = __shfl_xor_sync(~0u, b1i[s], x);
            float o2 = __shfl_xor_sync(~0u, b2v[s], x); u32 oi2 = __shfl_xor_sync(~0u, b2i[s], x);
            float o3 = __shfl_xor_sync(~0u, b3v[s], x); u32 oi3 = __shfl_xor_sync(~0u, b3i[s], x);
            float o4 = __shfl_xor_sync(~0u, b4v[s], x); u32 oi4 = __shfl_xor_sync(~0u, b4i[s], x);
            ins4(o1, oi1, b1v[s], b2v[s], b3v[s], b4v[s], b1i[s], b2i[s], b3i[s], b4i[s]);
            ins4(o2, oi2, b1v[s], b2v[s], b3v[s], b4v[s], b1i[s], b2i[s], b3i[s], b4i[s]);
            ins4(o3, oi3, b1v[s], b2v[s], b3v[s], b4v[s], b1i[s], b2i[s], b3i[s], b4i[s]);
            ins4(o4, oi4, b1v[s], b2v[s], b3v[s], b4v[s], b1i[s], b2i[s], b3i[s], b4i[s]);
        }
    }
    if ((lane & 3) == 0) {
#pragma unroll
        for (int s = 0; s < 4; s++) {
            int grow = wm * 32 + (s >> 1) * 16 + (s & 1) * 8 + (lane >> 2);
            r1v[wn * 128 + grow] = b1v[s]; r1i[wn * 128 + grow] = b1i[s];
            r2v[wn * 128 + grow] = b2v[s]; r2i[wn * 128 + grow] = b2i[s];
            r3v[wn * 128 + grow] = b3v[s]; r3i[wn * 128 + grow] = b3i[s];
            r4v[wn * 128 + grow] = b4v[s]; r4i[wn * 128 + grow] = b4i[s];
        }
    }
    __syncthreads();

    if (tid < 128) {
        float v1 = r1v[tid], v2 = r2v[tid], v3 = r3v[tid], v4 = r4v[tid];
        u32 i1 = r1i[tid], i2 = r2i[tid], i3 = r3i[tid], i4 = r4i[tid];
        ins4(r1v[128+tid], r1i[128+tid], v1, v2, v3, v4, i1, i2, i3, i4);
        ins4(r2v[128+tid], r2i[128+tid], v1, v2, v3, v4, i1, i2, i3, i4);
        ins4(r3v[128+tid], r3i[128+tid], v1, v2, v3, v4, i1, i2, i3, i4);
        ins4(r4v[128+tid], r4i[128+tid], v1, v2, v3, v4, i1, i2, i3, i4);
        const size_t tok = tokBase + tid;
        g_idx[tok] = i1;
        if (v2 - v1 < MARGIN) {
            if (v3 - v1 >= MARGIN) {          // exactly 2 candidates in window
                int p = atomicAdd(&g_npair, 1);
                g_pair[p] = (ull)tok | ((ull)i1 << 20) | ((ull)i2 << 32) | ((ull)i2 << 44);
            } else if (v4 - v1 >= MARGIN) {   // exactly 3 candidates in window
                int p = atomicAdd(&g_npair, 1);
                g_pair[p] = (ull)tok | ((ull)i1 << 20) | ((ull)i2 << 32) | ((ull)i3 << 44);
            } else {                          // >=4 possible candidates: full rescore
                int p = atomicAdd(&g_nfull, 1);
                g_full[p] = (u32)tok;
            }
        }
    }
}

// ---------------- exact rescore of up to 3 candidates (updates g_idx only) ----------------
__global__ __launch_bounds__(256) void rescue_kernel(
    const float* __restrict__ z, const float* __restrict__ cb)
{
    const int lane = threadIdx.x & 31;
    const int gw = (blockIdx.x * blockDim.x + threadIdx.x) >> 5;
    const int nw = (gridDim.x * blockDim.x) >> 5;
    const int n = g_npair;
    for (int i = gw; i < n; i += nw) {
        ull p = g_pair[i];
        u32 tok = (u32)(p & 0xFFFFFu);
        u32 c1 = (u32)((p >> 20) & 0x3FFu), c2 = (u32)((p >> 32) & 0x3FFu), c3 = (u32)((p >> 44) & 0x3FFu);
        const float4* zp = (const float4*)(z + (size_t)tok * DIMS + lane * 8);
        const float4* e1 = (const float4*)(cb + (size_t)c1 * DIMS + lane * 8);
        const float4* e2 = (const float4*)(cb + (size_t)c2 * DIMS + lane * 8);
        const float4* e3 = (const float4*)(cb + (size_t)c3 * DIMS + lane * 8);
        float4 za = zp[0], zb = zp[1];
        float4 a1 = e1[0], b1 = e1[1], a2 = e2[0], b2 = e2[1], a3 = e3[0], b3 = e3[1];
        float zsq = za.x*za.x, d1 = za.x*a1.x, d2 = za.x*a2.x, d3 = za.x*a3.x;
        zsq = fmaf(za.y, za.y, zsq); d1 = fmaf(za.y, a1.y, d1); d2 = fmaf(za.y, a2.y, d2); d3 = fmaf(za.y, a3.y, d3);
        zsq = fmaf(za.z, za.z, zsq); d1 = fmaf(za.z, a1.z, d1); d2 = fmaf(za.z, a2.z, d2); d3 = fmaf(za.z, a3.z, d3);
        zsq = fmaf(za.w, za.w, zsq); d1 = fmaf(za.w, a1.w, d1); d2 = fmaf(za.w, a2.w, d2); d3 = fmaf(za.w, a3.w, d3);
        zsq = fmaf(zb.x, zb.x, zsq); d1 = fmaf(zb.x, b1.x, d1); d2 = fmaf(zb.x, b2.x, d2); d3 = fmaf(zb.x, b3.x, d3);
        zsq = fmaf(zb.y, zb.y, zsq); d1 = fmaf(zb.y, b1.y, d1); d2 = fmaf(zb.y, b2.y, d2); d3 = fmaf(zb.y, b3.y, d3);
        zsq = fmaf(zb.z, zb.z, zsq); d1 = fmaf(zb.z, b1.z, d1); d2 = fmaf(zb.z, b2.z, d2); d3 = fmaf(zb.z, b3.z, d3);
        zsq = fmaf(zb.w, zb.w, zsq); d1 = fmaf(zb.w, b1.w, d1); d2 = fmaf(zb.w, b2.w, d2); d3 = fmaf(zb.w, b3.w, d3);
#pragma unroll
        for (int o = 16; o > 0; o >>= 1) {
            zsq += __shfl_xor_sync(~0u, zsq, o);
            d1 += __shfl_xor_sync(~0u, d1, o);
            d2 += __shfl_xor_sync(~0u, d2, o);
            d3 += __shfl_xor_sync(~0u, d3, o);
        }
        if (lane == 0) {
            float dd1 = __fmaf_rn(-2.f, d1, __fadd_rn(zsq, g_esq[c1]));
            float dd2 = __fmaf_rn(-2.f, d2, __fadd_rn(zsq, g_esq[c2]));
            float dd3 = __fmaf_rn(-2.f, d3, __fadd_rn(zsq, g_esq[c3]));
            ull k1 = ((ull)ordf(dd1) << 32) | c1;
            ull k2 = ((ull)ordf(dd2) << 32) | c2;
            ull k3 = ((ull)ordf(dd3) << 32) | c3;
            ull kb = k1 < k2 ? k1 : k2; if (k3 < kb) kb = k3;
            g_idx[tok] = (u32)(kb & 0xffffffffu);
        }
    }
}

// ---------------- exact full rescore: block-per-token (updates g_idx only) ----------------
__global__ __launch_bounds__(512) void full_kernel(
    const float* __restrict__ z, const float* __restrict__ cb)
{
    __shared__ float zrow[DIMS];
    __shared__ ull wb[16];
    const int t = threadIdx.x, lane = t & 31, w = t >> 5;
    const int n = g_nfull;
    for (int it = blockIdx.x; it < n; it += gridDim.x) {
        const u32 tok = g_full[it];
        if (t < DIMS) zrow[t] = z[(size_t)tok * DIMS + t];
        __syncthreads();
        float zr[8];
        const float* zp = &zrow[lane * 8];
#pragma unroll
        for (int i = 0; i < 8; i++) zr[i] = zp[i];
        float zsq = zr[0] * zr[0];
#pragma unroll
        for (int i = 1; i < 8; i++) zsq = fmaf(zr[i], zr[i], zsq);
#pragma unroll
        for (int o = 16; o > 0; o >>= 1) zsq += __shfl_xor_sync(~0u, zsq, o);

        ull best = ~0ull;
        const int cbase = w * 64;
#pragma unroll 2
        for (int j = 0; j < 64; j += 2) {
            const int ca = cbase + j, cbn = cbase + j + 1;
            const float4* ea = (const float4*)(cb + (size_t)ca * DIMS + lane * 8);
            const float4* eb = (const float4*)(cb + (size_t)cbn * DIMS + lane * 8);
            float4 a0 = ea[0], a1 = ea[1], b0 = eb[0], b1 = eb[1];
            float pa = zr[0] * a0.x, pb = zr[0] * b0.x;
            pa = fmaf(zr[1], a0.y, pa); pb = fmaf(zr[1], b0.y, pb);
            pa = fmaf(zr[2], a0.z, pa); pb = fmaf(zr[2], b0.z, pb);
            pa = fmaf(zr[3], a0.w, pa); pb = fmaf(zr[3], b0.w, pb);
            pa = fmaf(zr[4], a1.x, pa); pb = fmaf(zr[4], b1.x, pb);
            pa = fmaf(zr[5], a1.y, pa); pb = fmaf(zr[5], b1.y, pb);
            pa = fmaf(zr[6], a1.z, pa); pb = fmaf(zr[6], b1.z, pb);
            pa = fmaf(zr[7], a1.w, pa); pb = fmaf(zr[7], b1.w, pb);
#pragma unroll
            for (int o = 16; o > 0; o >>= 1) {
                pa += __shfl_xor_sync(~0u, pa, o);
                pb += __shfl_xor_sync(~0u, pb, o);
            }
            float da = __fmaf_rn(-2.f, pa, __fadd_rn(zsq, g_esq[ca]));
            float db = __fmaf_rn(-2.f, pb, __fadd_rn(zsq, g_esq[cbn]));
            ull ka = ((ull)ordf(da) << 32) | (u32)ca;
            ull kb = ((ull)ordf(db) << 32) | (u32)cbn;
            if (ka < best) best = ka;
            if (kb < best) best = kb;
        }
        if (lane == 0) wb[w] = best;
        __syncthreads();
        if (t == 0) {
            ull b = wb[0];
#pragma unroll
            for (int i = 1; i < 16; i++) if (wb[i] < b) b = wb[i];
            g_idx[tok] = (u32)(b & 0xffffffffu);
        }
        __syncthreads();
    }
}

// ---------------- final gather: z_q + indices from g_idx (DRAM-roofline) ----------------
__global__ __launch_bounds__(256) void gather_kernel(
    const float* __restrict__ cb, float* __restrict__ out_zq, float* __restrict__ out_idx)
{
    const int stride = gridDim.x * blockDim.x;
    const int total = NTOK * (DIMS / 4);
    for (int f = blockIdx.x * blockDim.x + threadIdx.x; f < total; f += stride) {
        const int tok = f >> 6, v = f & 63;
        const u32 idx = g_idx[tok];
        if (out_zq)
            ((float4*)out_zq)[f] = ((const float4*)(cb + (size_t)idx * DIMS))[v];
        if (out_idx && v == 0)
            out_idx[tok] = (float)idx;
    }
}

extern "C" void kernel_launch(void* const* d_in, const int* in_sizes, int n_in,
                              void* d_out, int out_size) {
    const float* z  = (const float*)d_in[0];
    const float* cb = (const float*)d_in[1];
    float* out = (float*)d_out;
    float* out_zq = nullptr;
    float* out_idx = nullptr;
    const long long ZQ = (long long)NTOK * DIMS;
    if ((long long)out_size >= ZQ + NTOK) { out_zq = out; out_idx = out + ZQ; }
    else if ((long long)out_size >= ZQ)   { out_zq = out; }
    else                                  { out_idx = out; }

    cudaFuncSetAttribute(vq_kernel, cudaFuncAttributeMaxDynamicSharedMemorySize, SMEM_BYTES);

    prep_kernel<<<NCODE, 256>>>(cb);
    vq_kernel<<<NTOK / TOKB, TPB, SMEM_BYTES>>>(z);
    rescue_kernel<<<1024, 256>>>(z, cb);
    full_kernel<<<512, 512>>>(z, cb);
    gather_kernel<<<2048, 256>>>(cb, out_zq, out_idx);
}

// round 15
// speedup vs baseline: 1.0265x; 1.0265x over previous
#include <cuda_runtime.h>
#include <cuda_fp16.h>
#include <cstdint>

#define NTOK   131072
#define DIMS   256
#define NCODE  1024
#define TOKB   128
#define TPB    256
#define NCH    32                 // codes per B chunk
#define NCHUNK (NCODE / NCH)      // 32
#define MARGIN 1e-4f
#define FULLBLKS 384              // fixup_kernel: blocks < FULLBLKS run full path

// smem layout (bytes)
#define SA    0                   // A: 128 rows x 256 fp16, stride 512B, swizzled = 64KB
#define SB    65536               // B: 2 x (32 rows x 256 fp16, stride 512B, swizzled) = 32KB
#define SBSZ  16384
#define SESQ  98304               // 1024 f32
#define SR1V  102400              // 2 N-groups x 128 rows each (1KB per array)
#define SR1I  103424
#define SR2V  104448
#define SR2I  105472
#define SR3V  106496
#define SR3I  107520
#define SR4V  108544
#define SR4I  109568
#define SIDX  110592
#define SMEM_BYTES 111104

typedef unsigned long long ull;
typedef unsigned int u32;

__device__ float g_esq[NCODE];
__device__ int   g_npair, g_nfull;
__device__ ull   g_pair[NTOK];
__device__ u32   g_full[NTOK];
__device__ __align__(16) __half g_Bh[(size_t)NCODE * DIMS];

__device__ __forceinline__ u32 s2u(const void* p) {
    u32 a; asm("{ .reg .u64 t; cvta.to.shared.u64 t, %1; cvt.u32.u64 %0, t; }" : "=r"(a) : "l"(p)); return a;
}
__device__ __forceinline__ void cpa16(u32 dst, const void* src) {
    asm volatile("cp.async.cg.shared.global [%0], [%1], 16;" :: "r"(dst), "l"(src));
}
#define CPA_COMMIT() asm volatile("cp.async.commit_group;" ::: "memory")
#define CPA_WAIT1()  asm volatile("cp.async.wait_group 1;"  ::: "memory")
#define CPA_WAIT0()  asm volatile("cp.async.wait_group 0;"  ::: "memory")

__device__ __forceinline__ void ldsm4(u32* r, u32 addr) {
    asm volatile("ldmatrix.sync.aligned.m8n8.x4.shared.b16 {%0,%1,%2,%3}, [%4];"
                 : "=r"(r[0]), "=r"(r[1]), "=r"(r[2]), "=r"(r[3]) : "r"(addr));
}
__device__ __forceinline__ void mma16816(float* c, const u32* a, const u32* b) {
    asm volatile("mma.sync.aligned.m16n8k16.row.col.f32.f16.f16.f32 "
                 "{%0,%1,%2,%3}, {%4,%5,%6,%7}, {%8,%9}, {%0,%1,%2,%3};"
                 : "+f"(c[0]), "+f"(c[1]), "+f"(c[2]), "+f"(c[3])
                 : "r"(a[0]), "r"(a[1]), "r"(a[2]), "r"(a[3]), "r"(b[0]), "r"(b[1]));
}
__device__ __forceinline__ u32 packh(float lo, float hi) {    // low 16 <- lo
    u32 r; asm("cvt.rn.f16x2.f32 %0, %1, %2;" : "=r"(r) : "f"(hi), "f"(lo)); return r;
}
__device__ __forceinline__ u32 ordf(float f) {
    u32 u = __float_as_uint(f);
    return (u & 0x80000000u) ? ~u : (u | 0x80000000u);
}
// streaming insert into sorted top-4 (with indices)
__device__ __forceinline__ void ins4(float m, u32 c,
    float &b1, float &b2, float &b3, float &b4,
    u32 &i1, u32 &i2, u32 &i3, u32 &i4)
{
    if (m < b4) {
        if (m < b3) {
            b4 = b3; i4 = i3;
            if (m < b2) {
                b3 = b2; i3 = i2;
                if (m < b1) { b2 = b1; i2 = i1; b1 = m; i1 = c; }
                else        { b2 = m; i2 = c; }
            } else { b3 = m; i3 = c; }
        } else { b4 = m; i4 = c; }
    }
}

// ---------------- merged prep: fp16 codebook + esq (warp-per-code) ----------------
__global__ __launch_bounds__(256) void prep_kernel(const float* __restrict__ cb) {
    const int tid = threadIdx.x, lane = tid & 31, w = tid >> 5;
    const int code = blockIdx.x * 8 + w;        // grid 128 x 8 warps
    if (blockIdx.x == 0 && tid == 0) { g_npair = 0; g_nfull = 0; }
    const float4* src = (const float4*)(cb + (size_t)code * DIMS + lane * 8);
    float4 a = src[0], b = src[1];
    float s = a.x * a.x;
    s = fmaf(a.y, a.y, s); s = fmaf(a.z, a.z, s); s = fmaf(a.w, a.w, s);
    s = fmaf(b.x, b.x, s); s = fmaf(b.y, b.y, s); s = fmaf(b.z, b.z, s);
    s = fmaf(b.w, b.w, s);
    u32 h0 = packh(a.x, a.y), h1 = packh(a.z, a.w), h2 = packh(b.x, b.y), h3 = packh(b.z, b.w);
    uint4* dst = (uint4*)(g_Bh + (size_t)code * DIMS + lane * 8);
    *dst = make_uint4(h0, h1, h2, h3);
#pragma unroll
    for (int o = 16; o > 0; o >>= 1) s += __shfl_xor_sync(~0u, s, o);
    if (lane == 0) g_esq[code] = s;
}

// ---------------- main: HMMA GEMM (fp16) + top-4 argmin, TOKB=128, occ 2 ----------------
__global__ __launch_bounds__(TPB, 2) void vq_kernel(
    const float* __restrict__ z, const float* __restrict__ cb,
    float* __restrict__ out_zq, float* __restrict__ out_idx)
{
    extern __shared__ __align__(16) unsigned char smem[];
    const u32 smb = s2u(smem);
    float* esq_s = (float*)(smem + SESQ);
    float* r1v = (float*)(smem + SR1V); u32* r1i = (u32*)(smem + SR1I);
    float* r2v = (float*)(smem + SR2V); u32* r2i = (u32*)(smem + SR2I);
    float* r3v = (float*)(smem + SR3V); u32* r3i = (u32*)(smem + SR3I);
    float* r4v = (float*)(smem + SR4V); u32* r4i = (u32*)(smem + SR4I);
    u32* idx_s = (u32*)(smem + SIDX);

    const int tid = threadIdx.x, lane = tid & 31, wid = tid >> 5;
    const int wm = wid & 3, wn = wid >> 2;      // 4 M-groups (32 rows) x 2 N-groups (16 codes)
    const size_t tokBase = (size_t)blockIdx.x * TOKB;

    // kick B chunk 0 (32 codes x 256 fp16 = 1024 x 16B)
#pragma unroll
    for (int i = 0; i < 4; i++) {
        int flat = tid + i * TPB, row = flat >> 5, g = flat & 31;
        u32 dst = smb + SB + (u32)row * 512 + (u32)((g ^ (row & 7)) << 4);
        cpa16(dst, g_Bh + ((size_t)row * DIMS + g * 8));
    }
    CPA_COMMIT();

    // A: convert z -> fp16 into smem (swizzled), 128 rows x 256
#pragma unroll
    for (int i = 0; i < 16; i++) {
        int flat = tid + i * TPB, row = flat >> 5, g = flat & 31;
        const float4* zp = (const float4*)(z + (tokBase + row) * DIMS + g * 8);
        float4 a = zp[0], b = zp[1];
        u32 h0 = packh(a.x, a.y), h1 = packh(a.z, a.w), h2 = packh(b.x, b.y), h3 = packh(b.z, b.w);
        u32 ah = smb + SA + (u32)row * 512 + (u32)((g ^ (row & 7)) << 4);
        asm volatile("st.shared.v4.b32 [%0], {%1,%2,%3,%4};" :: "r"(ah), "r"(h0), "r"(h1), "r"(h2), "r"(h3));
    }
#pragma unroll
    for (int i = 0; i < 4; i++) esq_s[tid + i * TPB] = g_esq[tid + i * TPB];

    // per-warp ldmatrix bases (fragment maps verified R4-R14)
    const int t8 = lane >> 3;
    u32 aBase[2]; int aSw[2];
#pragma unroll
    for (int mt = 0; mt < 2; mt++) {
        int ar = wm * 32 + mt * 16 + (t8 & 1) * 8 + (lane & 7);
        aSw[mt] = ar & 7; aBase[mt] = smb + SA + (u32)ar * 512;
    }
    const int akt = (lane >> 4) & 1;
    const int br = wn * 16 + (t8 >> 1) * 8 + (lane & 7);
    const int bSw = br & 7, bkt = t8 & 1;
    const u32 bRowOff = (u32)br * 512;

    // top-4 per row-slot (4 slots: mt*2 + acc-row-half)
    float b1v[4], b2v[4], b3v[4], b4v[4];
    u32 b1i[4], b2i[4], b3i[4], b4i[4];
#pragma unroll
    for (int s = 0; s < 4; s++) {
        b1v[s] = b2v[s] = b3v[s] = b4v[s] = 3.4e38f;
        b1i[s] = b2i[s] = b3i[s] = b4i[s] = 0;
    }

    for (int ch = 0; ch < NCHUNK; ch++) {
        if (ch < NCHUNK - 1) {
            const int nc = ch + 1;
#pragma unroll
            for (int i = 0; i < 4; i++) {
                int flat = tid + i * TPB, row = flat >> 5, g = flat & 31;
                u32 dst = smb + SB + (u32)((nc & 1) ? SBSZ : 0) + (u32)row * 512 + (u32)((g ^ (row & 7)) << 4);
                cpa16(dst, g_Bh + ((size_t)(nc * NCH + row) * DIMS + g * 8));
            }
            CPA_COMMIT();
            CPA_WAIT1();
        } else {
            CPA_WAIT0();
        }
        __syncthreads();

        const u32 bb = smb + SB + (u32)((ch & 1) ? SBSZ : 0) + bRowOff;
        float acc[2][2][4];
#pragma unroll
        for (int mt = 0; mt < 2; mt++)
#pragma unroll
            for (int nt = 0; nt < 2; nt++)
#pragma unroll
                for (int i = 0; i < 4; i++) acc[mt][nt][i] = 0.f;

        // software-pipelined fragments
        u32 bF[2][4], aF[2][2][4];
        ldsm4(bF[0], bb + (u32)(((0 + bkt) ^ bSw) << 4));
#pragma unroll
        for (int mt = 0; mt < 2; mt++)
            ldsm4(aF[0][mt], aBase[mt] + (u32)(((0 + akt) ^ aSw[mt]) << 4));

#pragma unroll
        for (int ks = 0; ks < 16; ks++) {
            const int cur = ks & 1, nxt = cur ^ 1;
            if (ks < 15) {
                const int k2 = (ks + 1) * 2;
                ldsm4(bF[nxt], bb + (u32)(((k2 + bkt) ^ bSw) << 4));
#pragma unroll
                for (int mt = 0; mt < 2; mt++)
                    ldsm4(aF[nxt][mt], aBase[mt] + (u32)(((k2 + akt) ^ aSw[mt]) << 4));
            }
#pragma unroll
            for (int mt = 0; mt < 2; mt++) {
                mma16816(acc[mt][0], aF[cur][mt], bF[cur]);
                mma16816(acc[mt][1], aF[cur][mt], bF[cur] + 2);
            }
        }

        // epilogue: m = esq - 2*dot, top-4 insert
#pragma unroll
        for (int mt = 0; mt < 2; mt++)
#pragma unroll
            for (int nt = 0; nt < 2; nt++)
#pragma unroll
                for (int i = 0; i < 4; i++) {
                    int c = ch * NCH + wn * 16 + nt * 8 + 2 * (lane & 3) + (i & 1);
                    float m = fmaf(-2.f, acc[mt][nt][i], esq_s[c]);
                    int s = mt * 2 + (i >> 1);
                    ins4(m, (u32)c, b1v[s], b2v[s], b3v[s], b4v[s],
                         b1i[s], b2i[s], b3i[s], b4i[s]);
                }
        __syncthreads();
    }

    // quad-lane merge (lanes sharing lane>>2 hold the same token row)
#pragma unroll
    for (int s = 0; s < 4; s++) {
#pragma unroll
        for (int x = 1; x <= 2; x <<= 1) {
            float o1 = __shfl_xor_sync(~0u, b1v[s], x); u32 oi1 = __shfl_xor_sync(~0u, b1i[s], x);
            float o2 = __shfl_xor_sync(~0u, b2v[s], x); u32 oi2 = __shfl_xor_sync(~0u, b2i[s], x);
            float o3 = __shfl_xor_sync(~0u, b3v[s], x); u32 oi3 = __shfl_xor_sync(~0u, b3i[s], x);
            float o4 = __shfl_xor_sync(~0u, b4v[s], x); u32 oi4 = __shfl_xor_sync(~0u, b4i[s], x);
            ins4(o1, oi1, b1v[s], b2v[s], b3v[s], b4v[s], b1i[s], b2i[s], b3i[s], b4i[s]);
            ins4(o2, oi2, b1v[s], b2v[s], b3v[s], b4v[s], b1i[s], b2i[s], b3i[s], b4i[s]);
            ins4(o3, oi3, b1v[s], b2v[s], b3v[s], b4v[s], b1i[s], b2i[s], b3i[s], b4i[s]);
            ins4(o4, oi4, b1v[s], b2v[s], b3v[s], b4v[s], b1i[s], b2i[s], b3i[s], b4i[s]);
        }
    }
    if ((lane & 3) == 0) {
#pragma unroll
        for (int s = 0; s < 4; s++) {
            int grow = wm * 32 + (s >> 1) * 16 + (s & 1) * 8 + (lane >> 2);
            r1v[wn * 128 + grow] = b1v[s]; r1i[wn * 128 + grow] = b1i[s];
            r2v[wn * 128 + grow] = b2v[s]; r2i[wn * 128 + grow] = b2i[s];
            r3v[wn * 128 + grow] = b3v[s]; r3i[wn * 128 + grow] = b3i[s];
            r4v[wn * 128 + grow] = b4v[s]; r4i[wn * 128 + grow] = b4i[s];
        }
    }
    __syncthreads();

    if (tid < 128) {
        float v1 = r1v[tid], v2 = r2v[tid], v3 = r3v[tid], v4 = r4v[tid];
        u32 i1 = r1i[tid], i2 = r2i[tid], i3 = r3i[tid], i4 = r4i[tid];
        ins4(r1v[128+tid], r1i[128+tid], v1, v2, v3, v4, i1, i2, i3, i4);
        ins4(r2v[128+tid], r2i[128+tid], v1, v2, v3, v4, i1, i2, i3, i4);
        ins4(r3v[128+tid], r3i[128+tid], v1, v2, v3, v4, i1, i2, i3, i4);
        ins4(r4v[128+tid], r4i[128+tid], v1, v2, v3, v4, i1, i2, i3, i4);
        const size_t tok = tokBase + tid;
        idx_s[tid] = i1;
        if (out_idx) out_idx[tok] = (float)i1;
        if (v2 - v1 < MARGIN) {
            if (v3 - v1 >= MARGIN) {          // exactly 2 candidates in window
                int p = atomicAdd(&g_npair, 1);
                g_pair[p] = (ull)tok | ((ull)i1 << 20) | ((ull)i2 << 32) | ((ull)i2 << 44);
            } else if (v4 - v1 >= MARGIN) {   // exactly 3 candidates in window
                int p = atomicAdd(&g_npair, 1);
                g_pair[p] = (ull)tok | ((ull)i1 << 20) | ((ull)i2 << 32) | ((ull)i3 << 44);
            } else {                          // >=4 possible candidates: full rescore
                int p = atomicAdd(&g_nfull, 1);
                g_full[p] = (u32)tok;
            }
        }
    }
    __syncthreads();

    if (out_zq) {
#pragma unroll
        for (int i = 0; i < 32; i++) {
            int flat = tid + i * TPB, t = flat >> 6, v = flat & 63;
            ((float4*)(out_zq + (tokBase + t) * DIMS))[v] =
                ((const float4*)(cb + (size_t)idx_s[t] * DIMS))[v];
        }
    }
}

// ---------------- merged exact fixup: full (blocks < FULLBLKS) + rescue (rest) ----------------
__global__ __launch_bounds__(512) void fixup_kernel(
    const float* __restrict__ z, const float* __restrict__ cb,
    float* __restrict__ out_zq, float* __restrict__ out_idx)
{
    if (blockIdx.x < FULLBLKS) {
        // ---- full rescore: block-per-token, 16 warps x 64 codes, ILP-2 ----
        __shared__ float zrow[DIMS];
        __shared__ ull wb[16];
        __shared__ u32 ridx;
        const int t = threadIdx.x, lane = t & 31, w = t >> 5;
        const int n = g_nfull;
        for (int it = blockIdx.x; it < n; it += FULLBLKS) {
            const u32 tok = g_full[it];
            if (t < DIMS) zrow[t] = z[(size_t)tok * DIMS + t];
            __syncthreads();
            float zr[8];
            const float* zp = &zrow[lane * 8];
#pragma unroll
            for (int i = 0; i < 8; i++) zr[i] = zp[i];
            float zsq = zr[0] * zr[0];
#pragma unroll
            for (int i = 1; i < 8; i++) zsq = fmaf(zr[i], zr[i], zsq);
#pragma unroll
            for (int o = 16; o > 0; o >>= 1) zsq += __shfl_xor_sync(~0u, zsq, o);

            ull best = ~0ull;
            const int cbase = w * 64;
#pragma unroll 2
            for (int j = 0; j < 64; j += 2) {
                const int ca = cbase + j, cbn = cbase + j + 1;
                const float4* ea = (const float4*)(cb + (size_t)ca * DIMS + lane * 8);
                const float4* eb = (const float4*)(cb + (size_t)cbn * DIMS + lane * 8);
                float4 a0 = ea[0], a1 = ea[1], b0 = eb[0], b1 = eb[1];
                float pa = zr[0] * a0.x, pb = zr[0] * b0.x;
                pa = fmaf(zr[1], a0.y, pa); pb = fmaf(zr[1], b0.y, pb);
                pa = fmaf(zr[2], a0.z, pa); pb = fmaf(zr[2], b0.z, pb);
                pa = fmaf(zr[3], a0.w, pa); pb = fmaf(zr[3], b0.w, pb);
                pa = fmaf(zr[4], a1.x, pa); pb = fmaf(zr[4], b1.x, pb);
                pa = fmaf(zr[5], a1.y, pa); pb = fmaf(zr[5], b1.y, pb);
                pa = fmaf(zr[6], a1.z, pa); pb = fmaf(zr[6], b1.z, pb);
                pa = fmaf(zr[7], a1.w, pa); pb = fmaf(zr[7], b1.w, pb);
#pragma unroll
                for (int o = 16; o > 0; o >>= 1) {
                    pa += __shfl_xor_sync(~0u, pa, o);
                    pb += __shfl_xor_sync(~0u, pb, o);
                }
                float da = __fmaf_rn(-2.f, pa, __fadd_rn(zsq, g_esq[ca]));
                float db = __fmaf_rn(-2.f, pb, __fadd_rn(zsq, g_esq[cbn]));
                ull ka = ((ull)ordf(da) << 32) | (u32)ca;
                ull kb = ((ull)ordf(db) << 32) | (u32)cbn;
                if (ka < best) best = ka;
                if (kb < best) best = kb;
            }
            if (lane == 0) wb[w] = best;
            __syncthreads();
            if (t == 0) {
                ull b = wb[0];
#pragma unroll
                for (int i = 1; i < 16; i++) if (wb[i] < b) b = wb[i];
                ridx = (u32)(b & 0xffffffffu);
                if (out_idx) out_idx[tok] = (float)ridx;
            }
            __syncthreads();
            if (out_zq && t < 64)
                ((float4*)(out_zq + (size_t)tok * DIMS))[t] = ((const float4*)(cb + (size_t)ridx * DIMS))[t];
            __syncthreads();
        }
    } else {
        // ---- rescue: warp-per-flagged-token, up to 3 exact candidates ----
        const int lane = threadIdx.x & 31;
        const int gw = ((blockIdx.x - FULLBLKS) * blockDim.x + threadIdx.x) >> 5;
        const int nw = ((gridDim.x - FULLBLKS) * blockDim.x) >> 5;
        const int n = g_npair;
        for (int i = gw; i < n; i += nw) {
            ull p = g_pair[i];
            u32 tok = (u32)(p & 0xFFFFFu);
            u32 c1 = (u32)((p >> 20) & 0x3FFu), c2 = (u32)((p >> 32) & 0x3FFu), c3 = (u32)((p >> 44) & 0x3FFu);
            const float4* zp = (const float4*)(z + (size_t)tok * DIMS + lane * 8);
            const float4* e1 = (const float4*)(cb + (size_t)c1 * DIMS + lane * 8);
            const float4* e2 = (const float4*)(cb + (size_t)c2 * DIMS + lane * 8);
            const float4* e3 = (const float4*)(cb + (size_t)c3 * DIMS + lane * 8);
            float4 za = zp[0], zb = zp[1];
            float4 a1 = e1[0], b1 = e1[1], a2 = e2[0], b2 = e2[1], a3 = e3[0], b3 = e3[1];
            float zsq = za.x*za.x, d1 = za.x*a1.x, d2 = za.x*a2.x, d3 = za.x*a3.x;
            zsq = fmaf(za.y, za.y, zsq); d1 = fmaf(za.y, a1.y, d1); d2 = fmaf(za.y, a2.y, d2); d3 = fmaf(za.y, a3.y, d3);
            zsq = fmaf(za.z, za.z, zsq); d1 = fmaf(za.z, a1.z, d1); d2 = fmaf(za.z, a2.z, d2); d3 = fmaf(za.z, a3.z, d3);
            zsq = fmaf(za.w, za.w, zsq); d1 = fmaf(za.w, a1.w, d1); d2 = fmaf(za.w, a2.w, d2); d3 = fmaf(za.w, a3.w, d3);
            zsq = fmaf(zb.x, zb.x, zsq); d1 = fmaf(zb.x, b1.x, d1); d2 = fmaf(zb.x, b2.x, d2); d3 = fmaf(zb.x, b3.x, d3);
            zsq = fmaf(zb.y, zb.y, zsq); d1 = fmaf(zb.y, b1.y, d1); d2 = fmaf(zb.y, b2.y, d2); d3 = fmaf(zb.y, b3.y, d3);
            zsq = fmaf(zb.z, zb.z, zsq); d1 = fmaf(zb.z, b1.z, d1); d2 = fmaf(zb.z, b2.z, d2); d3 = fmaf(zb.z, b3.z, d3);
            zsq = fmaf(zb.w, zb.w, zsq); d1 = fmaf(zb.w, b1.w, d1); d2 = fmaf(zb.w, b2.w, d2); d3 = fmaf(zb.w, b3.w, d3);
#pragma unroll
            for (int o = 16; o > 0; o >>= 1) {
                zsq += __shfl_xor_sync(~0u, zsq, o);
                d1 += __shfl_xor_sync(~0u, d1, o);
                d2 += __shfl_xor_sync(~0u, d2, o);
                d3 += __shfl_xor_sync(~0u, d3, o);
            }
            float dd1 = __fmaf_rn(-2.f, d1, __fadd_rn(zsq, g_esq[c1]));
            float dd2 = __fmaf_rn(-2.f, d2, __fadd_rn(zsq, g_esq[c2]));
            float dd3 = __fmaf_rn(-2.f, d3, __fadd_rn(zsq, g_esq[c3]));
            ull k1 = ((ull)ordf(dd1) << 32) | c1;
            ull k2 = ((ull)ordf(dd2) << 32) | c2;
            ull k3 = ((ull)ordf(dd3) << 32) | c3;
            ull kb = k1 < k2 ? k1 : k2; if (k3 < kb) kb = k3;
            u32 widx = (u32)(kb & 0xffffffffu);
            if (out_idx && lane == 0) out_idx[tok] = (float)widx;
            if (out_zq) {
                const float4* src = (const float4*)(cb + (size_t)widx * DIMS);
                float4* dst = (float4*)(out_zq + (size_t)tok * DIMS);
                dst[lane] = src[lane];
                dst[lane + 32] = src[lane + 32];
            }
        }
    }
}

extern "C" void kernel_launch(void* const* d_in, const int* in_sizes, int n_in,
                              void* d_out, int out_size) {
    const float* z  = (const float*)d_in[0];
    const float* cb = (const float*)d_in[1];
    float* out = (float*)d_out;
    float* out_zq = nullptr;
    float* out_idx = nullptr;
    const long long ZQ = (long long)NTOK * DIMS;
    if ((long long)out_size >= ZQ + NTOK) { out_zq = out; out_idx = out + ZQ; }
    else if ((long long)out_size >= ZQ)   { out_zq = out; }
    else                                  { out_idx = out; }

    cudaFuncSetAttribute(vq_kernel, cudaFuncAttributeMaxDynamicSharedMemorySize, SMEM_BYTES);

    prep_kernel<<<128, 256>>>(cb);
    vq_kernel<<<NTOK / TOKB, TPB, SMEM_BYTES>>>(z, cb, out_zq, out_idx);
    fixup_kernel<<<1024, 512>>>(z, cb, out_zq, out_idx);
}